// round 1
// baseline (speedup 1.0000x reference)
#include <cuda_runtime.h>

#define OMEGA_ENC 0.01f
#define OMEGA_K   0.1f
#define HD   64
#define FD   67
#define LATD 32
#define DIMD 3
#define N0MAX 4096
#define N1MAX 1024
#define EPB 4

// ---------------- scratch (static device globals; no allocation) ----------------
__device__ float g_xf0[N0MAX*FD];
__device__ float g_acc0[N0MAX*HD];
__device__ float g_h1[N0MAX*HD];
__device__ float g_pool[N0MAX*HD];
__device__ float g_xf1[N1MAX*FD];
__device__ float g_acc1[N1MAX*HD];
__device__ float g_h2[N1MAX*HD];

// ---------------- packed f32x2 helpers ----------------
__device__ __forceinline__ unsigned long long pack2(float a){
    unsigned long long r;
    asm("mov.b64 %0, {%1, %1};" : "=l"(r) : "r"(__float_as_uint(a)));
    return r;
}
__device__ __forceinline__ void fma2(unsigned long long& d, unsigned long long a, unsigned long long b){
    asm("fma.rn.f32x2 %0, %1, %2, %0;" : "+l"(d) : "l"(a), "l"(b));
}
__device__ __forceinline__ void unpack2(unsigned long long v, float& lo, float& hi){
    unsigned int l, h;
    asm("mov.b64 {%0, %1}, %2;" : "=r"(l), "=r"(h) : "l"(v));
    lo = __uint_as_float(l); hi = __uint_as_float(h);
}

// ---------------- init ----------------
__global__ void k_init(int n0, int n1){
    int i = blockIdx.x*blockDim.x + threadIdx.x;
    if (i < n0*HD){ g_acc0[i] = 0.f; g_pool[i] = __int_as_float(0xff800000); }
    if (i < n1*HD){ g_acc1[i] = 0.f; }
}

// ---------------- encoder: xf0 = [sin(w_enc*(x@W+b)) || pos] ----------------
__global__ void k_enc(const float* __restrict__ x, const float* __restrict__ pos,
                      const float* __restrict__ w, const float* __restrict__ b){
    int i = blockIdx.x; int t = threadIdx.x;
    float s = b[t];
    #pragma unroll
    for (int f = 0; f < 8; f++) s += x[i*8+f]*w[f*HD+t];
    g_xf0[i*FD+t] = __sinf(OMEGA_ENC*s);
    if (t < DIMD) g_xf0[i*FD+HD+t] = pos[i*DIMD+t];
}

// ---------------- kernel conv over edges (incl. appended self loops) ----------------
__global__ __launch_bounds__(EPB*HD) void k_conv(
    const float* __restrict__ xf, const float* __restrict__ pos,
    const int* __restrict__ ei, int E, int Etot,
    const float* __restrict__ w0, const float* __restrict__ b0,
    const float* __restrict__ w1, const float* __restrict__ b1,
    const float* __restrict__ w2, const float* __restrict__ b2,
    float* __restrict__ acc)
{
    __shared__ __align__(16) float w1s[HD*HD];   // 0.1*w1
    __shared__ float b1s[HD], w0ds[HD];
    __shared__ float base_s[EPB][HD], y_s[EPB][HD];
    __shared__ float ef[EPB][3];
    __shared__ int   esrc[EPB], edst[EPB];
    __shared__ float edotb[EPB];

    int tid = threadIdx.x;
    int eg = tid >> 6, c = tid & 63;
    int e = blockIdx.x*EPB + eg;
    bool act = (e < Etot);

    for (int i = tid; i < HD*HD; i += EPB*HD) w1s[i] = OMEGA_K*w1[i];
    if (tid < HD){ b1s[tid] = OMEGA_K*b1[tid]; w0ds[tid] = OMEGA_K*w0[3*HD+tid]; }

    if (act && c == 0){
        int src, dst;
        if (e < E){ src = ei[e]; dst = ei[E+e]; } else { src = e - E; dst = src; }
        float f0 = 0.f, f1 = 0.f, f2 = 0.f;
        if (e < E){
            float rx = pos[dst*3+0]-pos[src*3+0];
            float ry = pos[dst*3+1]-pos[src*3+1];
            float rz = pos[dst*3+2]-pos[src*3+2];
            if (!(rx == 0.f && ry == 0.f && rz == 0.f)){
                float rho = sqrtf(rx*rx+ry*ry+rz*rz);
                float th  = atan2f(ry, rx);
                float ratio = fminf(fmaxf(rz/rho, -1.f), 1.f);
                float ph  = asinf(ratio);
                const float inv_pi = 0.3183098861837907f;
                f0 = rho; f1 = th*inv_pi; f2 = ph*inv_pi;
            }
        }
        ef[eg][0] = f0; ef[eg][1] = f1; ef[eg][2] = f2;
        esrc[eg] = src; edst[eg] = dst;
    }
    __syncthreads();

    if (act){
        float f0 = ef[eg][0], f1 = ef[eg][1], f2 = ef[eg][2];
        base_s[eg][c] = OMEGA_K*(f0*w0[c] + f1*w0[HD+c] + f2*w0[2*HD+c] + b0[c]);
        const float* xr  = xf + esrc[eg]*FD;
        const float* w2r = w2 + c*FD;
        float y = 0.f;
        #pragma unroll
        for (int f = 0; f < FD; f++) y += w2r[f]*xr[f];
        y_s[eg][c] = y;
        if (c == 0){
            float db = 0.f;
            for (int f = 0; f < FD; f++) db += b2[f]*xr[f];
            edotb[eg] = db;
        }
    }
    __syncthreads();

    if (!act) return;

    unsigned long long a2acc[32];
    #pragma unroll
    for (int k = 0; k < 32; k++) a2acc[k] = 0ull;
    float cf = (float)c;
    const float* bs = base_s[eg];

    #pragma unroll 4
    for (int h = 0; h < HD; h++){
        float a = __sinf(fmaf(cf, w0ds[h], bs[h]));   // h0[c,h]
        unsigned long long a2 = pack2(a);
        const ulonglong2* wr = reinterpret_cast<const ulonglong2*>(&w1s[h << 6]);
        #pragma unroll
        for (int q = 0; q < 16; q++){
            ulonglong2 w = wr[q];
            fma2(a2acc[2*q+0], a2, w.x);   // k = 4q, 4q+1
            fma2(a2acc[2*q+1], a2, w.y);   // k = 4q+2, 4q+3
        }
    }

    float msg = edotb[eg];
    const float* ys = y_s[eg];
    #pragma unroll
    for (int q = 0; q < 32; q++){
        float lo, hi; unpack2(a2acc[q], lo, hi);
        msg += __sinf(lo + b1s[2*q+0]) * ys[2*q+0];
        msg += __sinf(hi + b1s[2*q+1]) * ys[2*q+1];
    }
    atomicAdd(&acc[edst[eg]*HD + c], msg);
}

// ---------------- post: out = sin(0.01*(acc + bias[c])) ----------------
__global__ void k_post(const float* __restrict__ acc, const float* __restrict__ bias,
                       float* __restrict__ out, int n){
    int i = blockIdx.x*blockDim.x + threadIdx.x;
    if (i < n) out[i] = __sinf(OMEGA_ENC*(acc[i] + bias[i & 63]));
}

// ---------------- neighbor max-pool ----------------
__device__ __forceinline__ void atomicMaxF(float* addr, float v){
    if (__float_as_uint(v) == 0x80000000u) v = 0.f;   // canonicalize -0.0
    if (v >= 0.f) atomicMax((int*)addr, __float_as_int(v));
    else          atomicMin((unsigned int*)addr, __float_as_uint(v));
}

__global__ void k_pool(const int* __restrict__ ei, int E, int Etot){
    int idx = blockIdx.x*blockDim.x + threadIdx.x;
    int e = idx >> 6, c = idx & 63;
    if (e >= Etot) return;
    int src, dst;
    if (e < E){ src = ei[e]; dst = ei[E+e]; } else { src = e - E; dst = src; }
    atomicMaxF(&g_pool[dst*HD + c], g_h1[src*HD + c]);
}

// ---------------- gather keep_idx + concat pos1 ----------------
__global__ void k_xf1(const int* __restrict__ keep, const float* __restrict__ pos1){
    int j = blockIdx.x, t = threadIdx.x;
    if (t < HD)      g_xf1[j*FD+t] = g_pool[keep[j]*HD + t];
    else if (t < FD) g_xf1[j*FD+t] = pos1[j*DIMD + (t - HD)];
}

// ---------------- final linear + sin ----------------
__global__ void k_final(const float* __restrict__ w, const float* __restrict__ b,
                        float* __restrict__ out){
    int j = blockIdx.x, l = threadIdx.x;
    float s = b[l];
    #pragma unroll
    for (int c = 0; c < HD; c++) s += g_h2[j*HD+c]*w[c*LATD+l];
    out[j*LATD+l] = __sinf(OMEGA_ENC*s);
}

// ---------------- launch ----------------
extern "C" void kernel_launch(void* const* d_in, const int* in_sizes, int n_in,
                              void* d_out, int out_size){
    // resolve input ordering: dict order (x,pos,edge_index,...) vs signature order
    // (x,edge_index,pos,...). pos has 3*N0 elems; edge_index has 2*E0 == 8*N0/... check sizes.
    int iPos = 1, iEi = 2;
    if (in_sizes[1] == in_sizes[0]) { iEi = 1; iPos = 2; }   // edge_index (2*16384) matches x (4096*8)

    const float* x      = (const float*)d_in[0];
    const float* pos    = (const float*)d_in[iPos];
    const int*   ei     = (const int*)  d_in[iEi];
    const int*   ei1    = (const int*)  d_in[3];
    const float* pos1   = (const float*)d_in[4];
    const int*   keep   = (const int*)  d_in[5];
    const float* lin0_w = (const float*)d_in[6];
    const float* lin0_b = (const float*)d_in[7];
    const float* lin1_w = (const float*)d_in[8];
    const float* lin1_b = (const float*)d_in[9];
    const float* c0p[7]; for (int i = 0; i < 7; i++) c0p[i] = (const float*)d_in[10+i];
    const float* c1p[7]; for (int i = 0; i < 7; i++) c1p[i] = (const float*)d_in[17+i];

    int N0 = in_sizes[0] / 8;
    int E0 = in_sizes[iEi] / 2;
    int N1 = in_sizes[5];
    int E1 = in_sizes[3] / 2;
    int Et0 = E0 + N0, Et1 = E1 + N1;
    float* out = (float*)d_out;

    float *xf0, *acc0, *h1, *xf1, *acc1, *h2;
    cudaGetSymbolAddress((void**)&xf0,  g_xf0);
    cudaGetSymbolAddress((void**)&acc0, g_acc0);
    cudaGetSymbolAddress((void**)&h1,   g_h1);
    cudaGetSymbolAddress((void**)&xf1,  g_xf1);
    cudaGetSymbolAddress((void**)&acc1, g_acc1);
    cudaGetSymbolAddress((void**)&h2,   g_h2);

    k_init<<<(N0*HD + 255)/256, 256>>>(N0, N1);
    k_enc <<<N0, HD>>>(x, pos, lin0_w, lin0_b);

    k_conv<<<(Et0 + EPB - 1)/EPB, EPB*HD>>>(xf0, pos, ei, E0, Et0,
        c0p[0], c0p[1], c0p[2], c0p[3], c0p[4], c0p[5], acc0);
    k_post<<<(N0*HD + 255)/256, 256>>>(acc0, c0p[6], h1, N0*HD);

    k_pool<<<(Et0*HD + 255)/256, 256>>>(ei, E0, Et0);
    k_xf1 <<<N1, 96>>>(keep, pos1);

    k_conv<<<(Et1 + EPB - 1)/EPB, EPB*HD>>>(xf1, pos1, ei1, E1, Et1,
        c1p[0], c1p[1], c1p[2], c1p[3], c1p[4], c1p[5], acc1);
    k_post<<<(N1*HD + 255)/256, 256>>>(acc1, c1p[6], h2, N1*HD);

    k_final<<<N1, LATD>>>(lin1_w, lin1_b, out);
}

// round 2
// speedup vs baseline: 1.2927x; 1.2927x over previous
#include <cuda_runtime.h>

#define OMEGA_ENC 0.01f
#define OMEGA_K   0.1f
#define HD   64
#define FD   67
#define LATD 32
#define DIMD 3
#define N0MAX 4096
#define N1MAX 1024
#define EPB  8            // edges per block (256 threads, 2 edges per thread)

// ---------------- scratch (static device globals; no allocation) ----------------
__device__ float g_xf0[N0MAX*FD];
__device__ float g_acc0[N0MAX*HD];
__device__ float g_h1[N0MAX*HD];
__device__ float g_pool[N0MAX*HD];
__device__ float g_xf1[N1MAX*FD];
__device__ float g_acc1[N1MAX*HD];
__device__ float g_h2[N1MAX*HD];

// ---------------- packed f32x2 helpers ----------------
__device__ __forceinline__ unsigned long long pack2(float a){
    unsigned long long r;
    asm("mov.b64 %0, {%1, %1};" : "=l"(r) : "r"(__float_as_uint(a)));
    return r;
}
__device__ __forceinline__ void fma2(unsigned long long& d, unsigned long long a, unsigned long long b){
    asm("fma.rn.f32x2 %0, %1, %2, %0;" : "+l"(d) : "l"(a), "l"(b));
}
__device__ __forceinline__ void unpack2(unsigned long long v, float& lo, float& hi){
    unsigned int l, h;
    asm("mov.b64 {%0, %1}, %2;" : "=r"(l), "=r"(h) : "l"(v));
    lo = __uint_as_float(l); hi = __uint_as_float(h);
}

// ---------------- init ----------------
__global__ void k_init(int n0, int n1){
    int i = blockIdx.x*blockDim.x + threadIdx.x;
    if (i < n0*HD){ g_acc0[i] = 0.f; g_pool[i] = __int_as_float(0xff800000); }
    if (i < n1*HD){ g_acc1[i] = 0.f; }
}

// ---------------- encoder: xf0 = [sin(w_enc*(x@W+b)) || pos] ----------------
__global__ void k_enc(const float* __restrict__ x, const float* __restrict__ pos,
                      const float* __restrict__ w, const float* __restrict__ b){
    int i = blockIdx.x; int t = threadIdx.x;
    float s = b[t];
    #pragma unroll
    for (int f = 0; f < 8; f++) s += x[i*8+f]*w[f*HD+t];
    g_xf0[i*FD+t] = sinf(OMEGA_ENC*s);           // accurate sin (tiny args)
    if (t < DIMD) g_xf0[i*FD+HD+t] = pos[i*DIMD+t];
}

// ---------------- kernel conv over edges (incl. appended self loops) ----------------
// Block: 256 threads. Thread (p = tid>>6, c = tid&63) processes edges
// eA = blk*8 + p and eB = eA + 4 for output channel c.  Each w1 row loaded
// from smem feeds 64 packed FFMA2 (2 edges x 32), halving LDS per MAC.
__global__ __launch_bounds__(256, 1) void k_conv(
    const float* __restrict__ xf, const float* __restrict__ pos,
    const int* __restrict__ ei, int E, int Etot,
    const float* __restrict__ w0, const float* __restrict__ b0,
    const float* __restrict__ w1, const float* __restrict__ b1,
    const float* __restrict__ w2, const float* __restrict__ b2,
    float* __restrict__ acc)
{
    __shared__ __align__(16) float w1s[HD*HD];   // 0.1*w1
    __shared__ float b1s[HD], w0ds[HD];
    __shared__ float base_s[EPB][HD], y_s[EPB][HD];
    __shared__ float ef[EPB][3];
    __shared__ int   esrc[EPB], edst[EPB];
    __shared__ float edotb[EPB];

    int tid = threadIdx.x;
    int p = tid >> 6, c = tid & 63;
    int eA = blockIdx.x*EPB + p;
    int eB = eA + 4;
    bool actA = (eA < Etot), actB = (eB < Etot);

    for (int i = tid; i < HD*HD; i += 256) w1s[i] = OMEGA_K*w1[i];
    if (tid < HD){ b1s[tid] = OMEGA_K*b1[tid]; w0ds[tid] = OMEGA_K*w0[3*HD+tid]; }

    // per-edge geometry: one thread per edge slot
    if (tid < EPB){
        int e = blockIdx.x*EPB + tid;
        if (e < Etot){
            int src, dst;
            if (e < E){ src = ei[e]; dst = ei[E+e]; } else { src = e - E; dst = src; }
            float f0 = 0.f, f1 = 0.f, f2 = 0.f;
            if (e < E){
                float rx = pos[dst*3+0]-pos[src*3+0];
                float ry = pos[dst*3+1]-pos[src*3+1];
                float rz = pos[dst*3+2]-pos[src*3+2];
                if (!(rx == 0.f && ry == 0.f && rz == 0.f)){
                    float rho = sqrtf(rx*rx+ry*ry+rz*rz);
                    float th  = atan2f(ry, rx);
                    float ratio = fminf(fmaxf(rz/rho, -1.f), 1.f);
                    float ph  = asinf(ratio);
                    const float inv_pi = 0.3183098861837907f;
                    f0 = rho; f1 = th*inv_pi; f2 = ph*inv_pi;
                }
            }
            ef[tid][0] = f0; ef[tid][1] = f1; ef[tid][2] = f2;
            esrc[tid] = src; edst[tid] = dst;
        }
    }
    __syncthreads();

    // per-(slot,c) prologue: base and y = W2 row c . x_src  for both edge slots
    #pragma unroll
    for (int s = 0; s < 2; s++){
        int slot = p + 4*s;
        int e = blockIdx.x*EPB + slot;
        if (e >= Etot) continue;
        float f0 = ef[slot][0], f1 = ef[slot][1], f2 = ef[slot][2];
        base_s[slot][c] = OMEGA_K*(f0*w0[c] + f1*w0[HD+c] + f2*w0[2*HD+c] + b0[c]);
        const float* xr  = xf + esrc[slot]*FD;
        const float* w2r = w2 + c*FD;
        float y = 0.f;
        #pragma unroll
        for (int f = 0; f < FD; f++) y += w2r[f]*xr[f];
        y_s[slot][c] = y;
        if (c == 0){
            float db = 0.f;
            for (int f = 0; f < FD; f++) db += b2[f]*xr[f];
            edotb[slot] = db;
        }
    }
    __syncthreads();

    if (!actA) return;

    unsigned long long accA[32], accB[32];
    #pragma unroll
    for (int k = 0; k < 32; k++){ accA[k] = 0ull; accB[k] = 0ull; }
    float cf = (float)c;
    const float* bsA = base_s[p];
    const float* bsB = base_s[p+4];

    if (actB){
        #pragma unroll 2
        for (int h = 0; h < HD; h++){
            float t  = cf*w0ds[h];
            float aA = __sinf(t + bsA[h]);
            float aB = __sinf(t + bsB[h]);
            unsigned long long a2A = pack2(aA);
            unsigned long long a2B = pack2(aB);
            const ulonglong2* wr = reinterpret_cast<const ulonglong2*>(&w1s[h << 6]);
            #pragma unroll
            for (int q = 0; q < 16; q++){
                ulonglong2 w = wr[q];
                fma2(accA[2*q+0], a2A, w.x);
                fma2(accA[2*q+1], a2A, w.y);
                fma2(accB[2*q+0], a2B, w.x);
                fma2(accB[2*q+1], a2B, w.y);
            }
        }
    } else {
        #pragma unroll 2
        for (int h = 0; h < HD; h++){
            float aA = __sinf(fmaf(cf, w0ds[h], bsA[h]));
            unsigned long long a2A = pack2(aA);
            const ulonglong2* wr = reinterpret_cast<const ulonglong2*>(&w1s[h << 6]);
            #pragma unroll
            for (int q = 0; q < 16; q++){
                ulonglong2 w = wr[q];
                fma2(accA[2*q+0], a2A, w.x);
                fma2(accA[2*q+1], a2A, w.y);
            }
        }
    }

    {
        float msg = edotb[p];
        const float* ys = y_s[p];
        #pragma unroll
        for (int q = 0; q < 32; q++){
            float lo, hi; unpack2(accA[q], lo, hi);
            msg += __sinf(lo + b1s[2*q+0]) * ys[2*q+0];
            msg += __sinf(hi + b1s[2*q+1]) * ys[2*q+1];
        }
        atomicAdd(&acc[edst[p]*HD + c], msg);
    }
    if (actB){
        float msg = edotb[p+4];
        const float* ys = y_s[p+4];
        #pragma unroll
        for (int q = 0; q < 32; q++){
            float lo, hi; unpack2(accB[q], lo, hi);
            msg += __sinf(lo + b1s[2*q+0]) * ys[2*q+0];
            msg += __sinf(hi + b1s[2*q+1]) * ys[2*q+1];
        }
        atomicAdd(&acc[edst[p+4]*HD + c], msg);
    }
}

// ---------------- post: out = sin(0.01*(acc + bias[c])) ----------------
__global__ void k_post(const float* __restrict__ acc, const float* __restrict__ bias,
                       float* __restrict__ out, int n){
    int i = blockIdx.x*blockDim.x + threadIdx.x;
    if (i < n) out[i] = sinf(OMEGA_ENC*(acc[i] + bias[i & 63]));
}

// ---------------- neighbor max-pool ----------------
__device__ __forceinline__ void atomicMaxF(float* addr, float v){
    if (__float_as_uint(v) == 0x80000000u) v = 0.f;   // canonicalize -0.0
    if (v >= 0.f) atomicMax((int*)addr, __float_as_int(v));
    else          atomicMin((unsigned int*)addr, __float_as_uint(v));
}

__global__ void k_pool(const int* __restrict__ ei, int E, int Etot){
    int idx = blockIdx.x*blockDim.x + threadIdx.x;
    int e = idx >> 6, c = idx & 63;
    if (e >= Etot) return;
    int src, dst;
    if (e < E){ src = ei[e]; dst = ei[E+e]; } else { src = e - E; dst = src; }
    atomicMaxF(&g_pool[dst*HD + c], g_h1[src*HD + c]);
}

// ---------------- gather keep_idx + concat pos1 ----------------
__global__ void k_xf1(const int* __restrict__ keep, const float* __restrict__ pos1){
    int j = blockIdx.x, t = threadIdx.x;
    if (t < HD)      g_xf1[j*FD+t] = g_pool[keep[j]*HD + t];
    else if (t < FD) g_xf1[j*FD+t] = pos1[j*DIMD + (t - HD)];
}

// ---------------- final linear + sin ----------------
__global__ void k_final(const float* __restrict__ w, const float* __restrict__ b,
                        float* __restrict__ out){
    int j = blockIdx.x, l = threadIdx.x;
    float s = b[l];
    #pragma unroll
    for (int c = 0; c < HD; c++) s += g_h2[j*HD+c]*w[c*LATD+l];
    out[j*LATD+l] = sinf(OMEGA_ENC*s);            // accurate: output magnitude ~1e-3
}

// ---------------- launch ----------------
extern "C" void kernel_launch(void* const* d_in, const int* in_sizes, int n_in,
                              void* d_out, int out_size){
    int iPos = 1, iEi = 2;
    if (in_sizes[1] == in_sizes[0]) { iEi = 1; iPos = 2; }

    const float* x      = (const float*)d_in[0];
    const float* pos    = (const float*)d_in[iPos];
    const int*   ei     = (const int*)  d_in[iEi];
    const int*   ei1    = (const int*)  d_in[3];
    const float* pos1   = (const float*)d_in[4];
    const int*   keep   = (const int*)  d_in[5];
    const float* lin0_w = (const float*)d_in[6];
    const float* lin0_b = (const float*)d_in[7];
    const float* lin1_w = (const float*)d_in[8];
    const float* lin1_b = (const float*)d_in[9];
    const float* c0p[7]; for (int i = 0; i < 7; i++) c0p[i] = (const float*)d_in[10+i];
    const float* c1p[7]; for (int i = 0; i < 7; i++) c1p[i] = (const float*)d_in[17+i];

    int N0 = in_sizes[0] / 8;
    int E0 = in_sizes[iEi] / 2;
    int N1 = in_sizes[5];
    int E1 = in_sizes[3] / 2;
    int Et0 = E0 + N0, Et1 = E1 + N1;
    float* out = (float*)d_out;

    float *xf0, *acc0, *h1, *xf1, *acc1, *h2;
    cudaGetSymbolAddress((void**)&xf0,  g_xf0);
    cudaGetSymbolAddress((void**)&acc0, g_acc0);
    cudaGetSymbolAddress((void**)&h1,   g_h1);
    cudaGetSymbolAddress((void**)&xf1,  g_xf1);
    cudaGetSymbolAddress((void**)&acc1, g_acc1);
    cudaGetSymbolAddress((void**)&h2,   g_h2);

    k_init<<<(N0*HD + 255)/256, 256>>>(N0, N1);
    k_enc <<<N0, HD>>>(x, pos, lin0_w, lin0_b);

    k_conv<<<(Et0 + EPB - 1)/EPB, 256>>>(xf0, pos, ei, E0, Et0,
        c0p[0], c0p[1], c0p[2], c0p[3], c0p[4], c0p[5], acc0);
    k_post<<<(N0*HD + 255)/256, 256>>>(acc0, c0p[6], h1, N0*HD);

    k_pool<<<(Et0*HD + 255)/256, 256>>>(ei, E0, Et0);
    k_xf1 <<<N1, 96>>>(keep, pos1);

    k_conv<<<(Et1 + EPB - 1)/EPB, 256>>>(xf1, pos1, ei1, E1, Et1,
        c1p[0], c1p[1], c1p[2], c1p[3], c1p[4], c1p[5], acc1);
    k_post<<<(N1*HD + 255)/256, 256>>>(acc1, c1p[6], h2, N1*HD);

    k_final<<<N1, LATD>>>(lin1_w, lin1_b, out);
}

// round 4
// speedup vs baseline: 3.4602x; 2.6767x over previous
#include <cuda_runtime.h>
#include <cuda_fp16.h>
#include <cstdint>

#define OMEGA_ENC 0.01f
#define HD   64
#define LATD 32
#define SXF  68          // padded xf row stride (16B aligned)
#define N0MAX 4096
#define N1MAX 1024
#define ETMAX (16384 + 4096)   // max edges incl. self loops

// ---------------- scratch (static device globals; zero-init, no allocation) ----
__device__ float  g_xf0[N0MAX*SXF];
__device__ float  g_xf1[N1MAX*SXF];
__device__ float  g_acc0[N0MAX*HD];
__device__ float  g_acc1[N1MAX*HD];
__device__ float  g_h1[N0MAX*HD];
__device__ float  g_pool[N0MAX*HD];
__device__ float  g_h2[N1MAX*HD];
__device__ float4 g_feat[ETMAX];
__device__ int    g_src[ETMAX];
__device__ int    g_dst[ETMAX];
__device__ float  g_edb[ETMAX];
__device__ float  g_Y[ETMAX*HD];
__device__ __half g_Bt[2][8192];        // ldmatrix-tiled 0.1*w1 hi/lo per conv
__device__ float  g_w2p[2][HD*SXF];     // padded w2 per conv

// ---------------- helpers ----------------
__device__ __forceinline__ uint32_t smem_u32(const void* p){
    uint32_t a;
    asm("{ .reg .u64 t; cvta.to.shared.u64 t, %1; cvt.u32.u64 %0, t; }" : "=r"(a) : "l"(p));
    return a;
}
__device__ __forceinline__ void split2(float v0, float v1, uint32_t& hi, uint32_t& lo){
    __half2 h = __floats2half2_rn(v0, v1);
    float2 hf = __half22float2(h);
    __half2 l2 = __floats2half2_rn(v0 - hf.x, v1 - hf.y);
    hi = *reinterpret_cast<uint32_t*>(&h);
    lo = *reinterpret_cast<uint32_t*>(&l2);
}
__device__ __forceinline__ void mma16816(float* d, const uint32_t* a, uint32_t b0, uint32_t b1){
    asm volatile("mma.sync.aligned.m16n8k16.row.col.f32.f16.f16.f32 "
        "{%0,%1,%2,%3}, {%4,%5,%6,%7}, {%8,%9}, {%0,%1,%2,%3};"
        : "+f"(d[0]), "+f"(d[1]), "+f"(d[2]), "+f"(d[3])
        : "r"(a[0]), "r"(a[1]), "r"(a[2]), "r"(a[3]), "r"(b0), "r"(b1));
}

// ---------------- init ----------------
__global__ void k_init(int n0, int n1){
    int i = blockIdx.x*blockDim.x + threadIdx.x;
    if (i < n0*HD){ g_acc0[i] = 0.f; g_pool[i] = __int_as_float(0xff800000); }
    if (i < n1*HD){ g_acc1[i] = 0.f; }
}

// ---------------- prep: B tiles (0.1*w1 hi/lo, ldmatrix 8x8 tile layout) -------
// layout: [(k2*8+nt)*4 + tix][r(0..7)][c(0..7)] halves; tix: 0=hi kh0, 1=hi kh1,
// 2=lo kh0, 3=lo kh1.  element: h = k2*16 + (tix&1)*8 + r ; n = nt*8 + c.
__global__ void k_prepB(const float* __restrict__ w1a, const float* __restrict__ w1b){
    int i = blockIdx.x*blockDim.x + threadIdx.x;
    if (i >= 2*8192) return;
    int conv = i >> 13, j = i & 8191;
    int group4 = j >> 6, rc = j & 63;
    int tix = group4 & 3, gnt = group4 >> 2;
    int k2 = gnt >> 3, nt = gnt & 7;
    int r = rc >> 3, c = rc & 7;
    int h = k2*16 + (tix & 1)*8 + r;
    int n = nt*8 + c;
    const float* w1 = conv ? w1b : w1a;
    float v = 0.1f * w1[h*HD + n];
    __half hh = __float2half_rn(v);
    g_Bt[conv][j] = (tix < 2) ? hh : __float2half_rn(v - __half2float(hh));
}

// ---------------- prep: padded w2 ----------------
__global__ void k_prepW2(const float* __restrict__ w2a, const float* __restrict__ w2b){
    int i = blockIdx.x*blockDim.x + threadIdx.x;   // 2*64*68
    if (i >= 2*HD*SXF) return;
    int conv = i / (HD*SXF), j = i % (HD*SXF);
    int k = j / SXF, f = j % SXF;
    const float* w2 = conv ? w2b : w2a;
    g_w2p[conv][j] = (f < 67) ? w2[k*67 + f] : 0.f;
}

// ---------------- encoder ----------------
__global__ void k_enc(const float* __restrict__ x, const float* __restrict__ pos,
                      const float* __restrict__ w, const float* __restrict__ b){
    int i = blockIdx.x; int t = threadIdx.x;
    float s = b[t];
    #pragma unroll
    for (int f = 0; f < 8; f++) s += x[i*8+f]*w[f*HD+t];
    g_xf0[i*SXF+t] = sinf(OMEGA_ENC*s);
    if (t < 3) g_xf0[i*SXF+HD+t] = pos[i*3+t];
}

// ---------------- prep: per-edge geometry + edotb ----------------
__global__ void k_prepEdge(const int* __restrict__ ei, int E, int Etot,
                           const float* __restrict__ pos, const float* __restrict__ xf,
                           const float* __restrict__ b2){
    int eg = blockIdx.x*blockDim.x + threadIdx.x;
    if (eg >= Etot) return;
    int src, dst;
    float f0 = 0.f, f1 = 0.f, f2 = 0.f;
    if (eg < E){
        src = ei[eg]; dst = ei[E+eg];
        float rx = pos[dst*3+0]-pos[src*3+0];
        float ry = pos[dst*3+1]-pos[src*3+1];
        float rz = pos[dst*3+2]-pos[src*3+2];
        if (!(rx == 0.f && ry == 0.f && rz == 0.f)){
            float rho = sqrtf(rx*rx+ry*ry+rz*rz);
            float th  = atan2f(ry, rx);
            float ratio = fminf(fmaxf(rz/rho, -1.f), 1.f);
            float ph  = asinf(ratio);
            const float inv_pi = 0.3183098861837907f;
            f0 = rho; f1 = th*inv_pi; f2 = ph*inv_pi;
        }
    } else { src = eg - E; dst = src; }
    g_feat[eg] = make_float4(f0, f1, f2, 0.f);
    g_src[eg] = src; g_dst[eg] = dst;
    const float* xr = xf + src*SXF;
    float db = 0.f;
    for (int f = 0; f < 67; f++) db += b2[f]*xr[f];
    g_edb[eg] = db;
}

// ---------------- prep: Y[e,k] = w2[k,:] . xf[src_e] ----------------
__global__ void k_prepY(const float* __restrict__ xf, const float* __restrict__ w2p,
                        int Etot){
    int idx = blockIdx.x*blockDim.x + threadIdx.x;
    int eg = idx >> 6, k = idx & 63;
    if (eg >= Etot) return;
    const float4* xr = (const float4*)(xf + g_src[eg]*SXF);
    const float4* wr = (const float4*)(w2p + k*SXF);
    float y = 0.f;
    #pragma unroll
    for (int i = 0; i < 17; i++){
        float4 a = xr[i], b = wr[i];
        y += a.x*b.x + a.y*b.y + a.z*b.z + a.w*b.w;
    }
    g_Y[eg*HD + k] = y;
}

// ---------------- HMMA kernel conv ----------------
// Tile = 2 edges: rows m = 64e + c (c=0..63).  Warp w owns m-strips 32w, 32w+16.
// A[m,h] = sin(0.1*(base_e[h] + c*w0d[h])) generated in registers (fp16 hi/lo);
// B = 0.1*w1 hi/lo from smem via ldmatrix; D fp32 in accum regs.
// msg[e,c] = edb_e + sum_k sin(D[m,k] + 0.1 b1_k) * Y[e,k]; atomicAdd to acc.
__global__ __launch_bounds__(128, 4) void k_convTC(
    const float* __restrict__ w0, const float* __restrict__ b0,
    const float* __restrict__ b1, const __half* __restrict__ Bt,
    int Etot, int ntiles, float* __restrict__ acc)
{
    __shared__ __align__(16) __half smB[8192];
    __shared__ float sbase[2][64];
    __shared__ float sdel[64];
    __shared__ float sb1[64];

    const int tid = threadIdx.x;
    {
        const uint4* s = (const uint4*)Bt;
        uint4* d = (uint4*)smB;
        #pragma unroll
        for (int i = 0; i < 8; i++) d[tid + 128*i] = s[tid + 128*i];
    }
    if (tid < 64){ sdel[tid] = 0.1f*w0[192+tid]; sb1[tid] = 0.1f*b1[tid]; }

    const int hb = tid & 63;
    const float w0a = w0[hb], w0b_ = w0[64+hb], w0c = w0[128+hb], b0h = b0[hb];

    const int w = tid >> 5, l = tid & 31, g = l >> 2, t = l & 3;
    const int e  = w >> 1;
    const int cb = 32*(w & 1);
    const int e2 = tid >> 6;
    const uint32_t lm_base = smem_u32(smB) + (uint32_t)(((l >> 3)*64 + (l & 7)*8) * 2);

    __syncthreads();

    for (int tile = blockIdx.x; tile < ntiles; tile += gridDim.x){
        __syncthreads();
        {   // base generation: thread (e2, hb)
            int eg = 2*tile + e2;
            float4 ft = (eg < Etot) ? g_feat[eg] : make_float4(0.f,0.f,0.f,0.f);
            sbase[e2][hb] = 0.1f*(ft.x*w0a + ft.y*w0b_ + ft.z*w0c + b0h);
        }
        __syncthreads();

        float d[2][8][4];
        #pragma unroll
        for (int s = 0; s < 2; s++)
            #pragma unroll
            for (int n = 0; n < 8; n++)
                #pragma unroll
                for (int q = 0; q < 4; q++) d[s][n][q] = 0.f;

        #pragma unroll
        for (int k2 = 0; k2 < 4; k2++){
            const int hA = 2*t + 16*k2;
            float2 bA = *(const float2*)&sbase[e][hA];
            float2 dA = *(const float2*)&sdel[hA];
            float2 bB = *(const float2*)&sbase[e][hA+8];
            float2 dB = *(const float2*)&sdel[hA+8];

            uint32_t aH[2][4], aL[2][4];
            #pragma unroll
            for (int s = 0; s < 2; s++){
                float cf = (float)(cb + 16*s + g);
                float a00 = __sinf(fmaf(cf,     dA.x, bA.x));
                float a01 = __sinf(fmaf(cf,     dA.y, bA.y));
                float a10 = __sinf(fmaf(cf+8.f, dA.x, bA.x));
                float a11 = __sinf(fmaf(cf+8.f, dA.y, bA.y));
                float a20 = __sinf(fmaf(cf,     dB.x, bB.x));
                float a21 = __sinf(fmaf(cf,     dB.y, bB.y));
                float a30 = __sinf(fmaf(cf+8.f, dB.x, bB.x));
                float a31 = __sinf(fmaf(cf+8.f, dB.y, bB.y));
                split2(a00, a01, aH[s][0], aL[s][0]);
                split2(a10, a11, aH[s][1], aL[s][1]);
                split2(a20, a21, aH[s][2], aL[s][2]);
                split2(a30, a31, aH[s][3], aL[s][3]);
            }
            uint32_t lma = lm_base + (uint32_t)(k2*8)*512u;
            #pragma unroll
            for (int nt = 0; nt < 8; nt++){
                uint32_t r0, r1, r2, r3;
                asm volatile("ldmatrix.sync.aligned.m8n8.x4.trans.shared.b16 "
                             "{%0,%1,%2,%3}, [%4];"
                             : "=r"(r0), "=r"(r1), "=r"(r2), "=r"(r3) : "r"(lma));
                lma += 512u;
                #pragma unroll
                for (int s = 0; s < 2; s++){
                    mma16816(d[s][nt], aH[s], r0, r1);
                    mma16816(d[s][nt], aL[s], r0, r1);
                    mma16816(d[s][nt], aH[s], r2, r3);
                }
            }
        }

        // ---- epilogue ----
        int eg = 2*tile + e;
        bool val = (eg < Etot);
        float m00 = 0.f, m01 = 0.f, m10 = 0.f, m11 = 0.f;
        #pragma unroll
        for (int nt = 0; nt < 8; nt++){
            int col = 2*t + 8*nt;
            float2 bv = *(const float2*)&sb1[col];
            float2 yv = val ? *(const float2*)&g_Y[eg*HD + col] : make_float2(0.f, 0.f);
            m00 += __sinf(d[0][nt][0]+bv.x)*yv.x + __sinf(d[0][nt][1]+bv.y)*yv.y;
            m01 += __sinf(d[0][nt][2]+bv.x)*yv.x + __sinf(d[0][nt][3]+bv.y)*yv.y;
            m10 += __sinf(d[1][nt][0]+bv.x)*yv.x + __sinf(d[1][nt][1]+bv.y)*yv.y;
            m11 += __sinf(d[1][nt][2]+bv.x)*yv.x + __sinf(d[1][nt][3]+bv.y)*yv.y;
        }
        m00 += __shfl_xor_sync(~0u, m00, 1); m00 += __shfl_xor_sync(~0u, m00, 2);
        m01 += __shfl_xor_sync(~0u, m01, 1); m01 += __shfl_xor_sync(~0u, m01, 2);
        m10 += __shfl_xor_sync(~0u, m10, 1); m10 += __shfl_xor_sync(~0u, m10, 2);
        m11 += __shfl_xor_sync(~0u, m11, 1); m11 += __shfl_xor_sync(~0u, m11, 2);
        if (t == 0 && val){
            int dst = g_dst[eg];
            float eb = g_edb[eg];
            atomicAdd(&acc[dst*HD + cb + g     ], m00 + eb);
            atomicAdd(&acc[dst*HD + cb + g + 8 ], m01 + eb);
            atomicAdd(&acc[dst*HD + cb + g + 16], m10 + eb);
            atomicAdd(&acc[dst*HD + cb + g + 24], m11 + eb);
        }
    }
}

// ---------------- post / pool / gather / final ----------------
__global__ void k_post(const float* __restrict__ acc, const float* __restrict__ bias,
                       float* __restrict__ out, int n){
    int i = blockIdx.x*blockDim.x + threadIdx.x;
    if (i < n) out[i] = sinf(OMEGA_ENC*(acc[i] + bias[i & 63]));
}
__device__ __forceinline__ void atomicMaxF(float* addr, float v){
    if (__float_as_uint(v) == 0x80000000u) v = 0.f;
    if (v >= 0.f) atomicMax((int*)addr, __float_as_int(v));
    else          atomicMin((unsigned int*)addr, __float_as_uint(v));
}
__global__ void k_pool(int Etot){
    int idx = blockIdx.x*blockDim.x + threadIdx.x;
    int e = idx >> 6, c = idx & 63;
    if (e >= Etot) return;
    atomicMaxF(&g_pool[g_dst[e]*HD + c], g_h1[g_src[e]*HD + c]);
}
__global__ void k_xf1(const int* __restrict__ keep, const float* __restrict__ pos1){
    int j = blockIdx.x, t = threadIdx.x;
    if (t < HD)        g_xf1[j*SXF+t] = g_pool[keep[j]*HD + t];
    else if (t < HD+3) g_xf1[j*SXF+t] = pos1[j*3 + (t - HD)];
}
__global__ void k_final(const float* __restrict__ w, const float* __restrict__ b,
                        float* __restrict__ out){
    int j = blockIdx.x, l = threadIdx.x;
    float s = b[l];
    #pragma unroll
    for (int c = 0; c < HD; c++) s += g_h2[j*HD+c]*w[c*LATD+l];
    out[j*LATD+l] = sinf(OMEGA_ENC*s);
}

// ---------------- launch ----------------
extern "C" void kernel_launch(void* const* d_in, const int* in_sizes, int n_in,
                              void* d_out, int out_size){
    int iPos = 1, iEi = 2;
    if (in_sizes[1] == in_sizes[0]) { iEi = 1; iPos = 2; }

    const float* x      = (const float*)d_in[0];
    const float* pos    = (const float*)d_in[iPos];
    const int*   ei     = (const int*)  d_in[iEi];
    const int*   ei1    = (const int*)  d_in[3];
    const float* pos1   = (const float*)d_in[4];
    const int*   keep   = (const int*)  d_in[5];
    const float* lin0_w = (const float*)d_in[6];
    const float* lin0_b = (const float*)d_in[7];
    const float* lin1_w = (const float*)d_in[8];
    const float* lin1_b = (const float*)d_in[9];
    const float* c0p[7]; for (int i = 0; i < 7; i++) c0p[i] = (const float*)d_in[10+i];
    const float* c1p[7]; for (int i = 0; i < 7; i++) c1p[i] = (const float*)d_in[17+i];

    int N0 = in_sizes[0] / 8;
    int E0 = in_sizes[iEi] / 2;
    int N1 = in_sizes[5];
    int E1 = in_sizes[3] / 2;
    int Et0 = E0 + N0, Et1 = E1 + N1;
    int nt0 = (Et0 + 1)/2, nt1 = (Et1 + 1)/2;
    float* out = (float*)d_out;

    float *xf0, *acc0, *h1, *xf1, *acc1, *h2, *w2p;
    __half* bt;
    cudaGetSymbolAddress((void**)&xf0,  g_xf0);
    cudaGetSymbolAddress((void**)&acc0, g_acc0);
    cudaGetSymbolAddress((void**)&h1,   g_h1);
    cudaGetSymbolAddress((void**)&xf1,  g_xf1);
    cudaGetSymbolAddress((void**)&acc1, g_acc1);
    cudaGetSymbolAddress((void**)&h2,   g_h2);
    cudaGetSymbolAddress((void**)&bt,   g_Bt);
    cudaGetSymbolAddress((void**)&w2p,  g_w2p);

    int g0 = nt0 < 592 ? nt0 : 592;
    int g1 = nt1 < 592 ? nt1 : 592;

    k_init  <<<(N0*HD + 255)/256, 256>>>(N0, N1);
    k_prepB <<<64, 256>>>(c0p[2], c1p[2]);
    k_prepW2<<<(2*HD*SXF + 255)/256, 256>>>(c0p[4], c1p[4]);
    k_enc   <<<N0, HD>>>(x, pos, lin0_w, lin0_b);

    // ---- conv0 ----
    k_prepEdge<<<(Et0 + 127)/128, 128>>>(ei, E0, Et0, pos, xf0, c0p[5]);
    k_prepY   <<<(Et0*HD + 127)/128, 128>>>(xf0, w2p, Et0);
    k_convTC  <<<g0, 128>>>(c0p[0], c0p[1], c0p[3], bt, Et0, nt0, acc0);
    k_post    <<<(N0*HD + 255)/256, 256>>>(acc0, c0p[6], h1, N0*HD);

    // ---- pool (uses g_src/g_dst from conv0 prep) ----
    k_pool<<<(Et0*HD + 255)/256, 256>>>(Et0);
    k_xf1 <<<N1, 96>>>(keep, pos1);

    // ---- conv1 ----
    k_prepEdge<<<(Et1 + 127)/128, 128>>>(ei1, E1, Et1, pos1, xf1, c1p[5]);
    k_prepY   <<<(Et1*HD + 127)/128, 128>>>(xf1, w2p + HD*SXF, Et1);
    k_convTC  <<<g1, 128>>>(c1p[0], c1p[1], c1p[3], bt + 8192, Et1, nt1, acc1);
    k_post    <<<(N1*HD + 255)/256, 256>>>(acc1, c1p[6], h2, N1*HD);

    k_final<<<N1, LATD>>>(lin1_w, lin1_b, out);
}